// round 1
// baseline (speedup 1.0000x reference)
#include <cuda_runtime.h>
#include <math.h>

// ---------------- constants ----------------
#define Bdim 8
#define Ndim 1024
#define Ddim 1024
#define Hdim 16
#define DEPTH 64
#define MLPdim 4096
#define ROWS (Bdim * Ndim)          // 8192
#define EPSLN 1e-6f
#define INV_SQRT_DEPTH 0.125f

// ---------------- scratch (static device globals; no allocation) ----------------
__device__ float g_xn[ROWS * Ddim];        // 32 MB  (x_norm1, later x_norm2)
__device__ float g_q[ROWS * Ddim];         // 32 MB  (q, later r)
__device__ float g_k[ROWS * Ddim];         // 32 MB
__device__ float g_v[ROWS * Ddim];         // 32 MB
__device__ float g_ao[ROWS * Ddim];        // 32 MB  (attn_out)
__device__ float g_mlph[ROWS * MLPdim];    // 128 MB
__device__ float g_attn[Bdim * Hdim * Ndim];
__device__ float g_gq[Bdim * Hdim * DEPTH];
__device__ float g_h[Bdim * Ddim];
__device__ float g_scale[Bdim * Ddim];
__device__ float g_shift[Bdim * Ddim];

// ---------------- block reduction helpers ----------------
__device__ __forceinline__ float blockReduceSum(float v, float* smem) {
    #pragma unroll
    for (int o = 16; o; o >>= 1) v += __shfl_xor_sync(0xFFFFFFFFu, v, o);
    int wid = threadIdx.x >> 5;
    if ((threadIdx.x & 31) == 0) smem[wid] = v;
    __syncthreads();
    float r = 0.f;
    if (threadIdx.x < 8) r = smem[threadIdx.x];
    if (threadIdx.x < 8) {
        #pragma unroll
        for (int o = 4; o; o >>= 1) r += __shfl_xor_sync(0xFFu, r, o);
        if (threadIdx.x == 0) smem[0] = r;
    }
    __syncthreads();
    r = smem[0];
    __syncthreads();
    return r;
}

__device__ __forceinline__ float blockReduceMax(float v, float* smem) {
    #pragma unroll
    for (int o = 16; o; o >>= 1) v = fmaxf(v, __shfl_xor_sync(0xFFFFFFFFu, v, o));
    int wid = threadIdx.x >> 5;
    if ((threadIdx.x & 31) == 0) smem[wid] = v;
    __syncthreads();
    float r = -1e30f;
    if (threadIdx.x < 8) r = smem[threadIdx.x];
    if (threadIdx.x < 8) {
        #pragma unroll
        for (int o = 4; o; o >>= 1) r = fmaxf(r, __shfl_xor_sync(0xFFu, r, o));
        if (threadIdx.x == 0) smem[0] = r;
    }
    __syncthreads();
    r = smem[0];
    __syncthreads();
    return r;
}

// ---------------- big SGEMM: C[M,N] = epi(A[M,K] @ W[K,N] + bias) ----------------
// EPI: 0 = +bias ; 1 = +bias +res ; 2 = gelu(+bias)
#define BM 128
#define BN 128
#define BKT 8

template <int EPI>
__global__ __launch_bounds__(256)
void sgemm_kernel(const float* __restrict__ A, const float* __restrict__ W,
                  const float* __restrict__ bias, const float* __restrict__ res,
                  float* __restrict__ C, int M, int N, int K) {
    __shared__ float As[BKT][BM];
    __shared__ float Bs[BKT][BN];

    const int tid = threadIdx.x;
    const int brow = blockIdx.y;
    const int bcol = blockIdx.x;

    const float* Ab = A + (size_t)brow * BM * K;
    const float* Wb = W + (size_t)bcol * BN;

    const int aRow = tid >> 1;          // 0..127
    const int aCol = (tid & 1) * 4;     // 0 or 4
    const int bRow = tid >> 5;          // 0..7
    const int bCol = (tid & 31) * 4;    // 0..124
    const int tr = (tid >> 4) * 8;      // 0..120
    const int tc = (tid & 15) * 8;      // 0..120

    float acc[8][8];
    #pragma unroll
    for (int i = 0; i < 8; ++i)
        #pragma unroll
        for (int j = 0; j < 8; ++j) acc[i][j] = 0.f;

    for (int kt = 0; kt < K; kt += BKT) {
        float4 av = *reinterpret_cast<const float4*>(Ab + (size_t)aRow * K + kt + aCol);
        As[aCol + 0][aRow] = av.x;
        As[aCol + 1][aRow] = av.y;
        As[aCol + 2][aRow] = av.z;
        As[aCol + 3][aRow] = av.w;
        *reinterpret_cast<float4*>(&Bs[bRow][bCol]) =
            *reinterpret_cast<const float4*>(Wb + (size_t)(kt + bRow) * N + bCol);
        __syncthreads();

        #pragma unroll
        for (int k = 0; k < BKT; ++k) {
            float ar[8], br[8];
            #pragma unroll
            for (int i = 0; i < 8; ++i) ar[i] = As[k][tr + i];
            #pragma unroll
            for (int j = 0; j < 8; ++j) br[j] = Bs[k][tc + j];
            #pragma unroll
            for (int i = 0; i < 8; ++i)
                #pragma unroll
                for (int j = 0; j < 8; ++j) acc[i][j] = fmaf(ar[i], br[j], acc[i][j]);
        }
        __syncthreads();
    }

    #pragma unroll
    for (int i = 0; i < 8; ++i) {
        const int row = brow * BM + tr + i;
        #pragma unroll
        for (int j4 = 0; j4 < 2; ++j4) {
            const int col = bcol * BN + tc + j4 * 4;
            float4 o;
            float t[4];
            #pragma unroll
            for (int j = 0; j < 4; ++j) {
                float vv = acc[i][j4 * 4 + j] + bias[col + j];
                if (EPI == 1) vv += res[(size_t)row * N + col + j];
                if (EPI == 2) vv = 0.5f * vv * (1.f + erff(vv * 0.7071067811865475f));
                t[j] = vv;
            }
            o.x = t[0]; o.y = t[1]; o.z = t[2]; o.w = t[3];
            *reinterpret_cast<float4*>(C + (size_t)row * N + col) = o;
        }
    }
}

// ---------------- layernorm (no affine) + per-row scale/shift modulation ----------------
__global__ __launch_bounds__(256)
void ln_mod_kernel(const float* __restrict__ x, const float* __restrict__ scale,
                   const float* __restrict__ shift, float* __restrict__ out) {
    __shared__ float smem[8];
    const int row = blockIdx.x;          // 0..8191
    const int b = row >> 10;
    const int n = row & 1023;
    float4 v = reinterpret_cast<const float4*>(x + (size_t)row * Ddim)[threadIdx.x];
    float s = v.x + v.y + v.z + v.w;
    float mean = blockReduceSum(s, smem) * (1.f / Ddim);
    float dx = v.x - mean, dy = v.y - mean, dz = v.z - mean, dw = v.w - mean;
    float sq = dx * dx + dy * dy + dz * dz + dw * dw;
    float var = blockReduceSum(sq, smem) * (1.f / Ddim);
    float rstd = rsqrtf(var + EPSLN);
    float sc = scale[b * Ddim + n] * rstd;
    float sh = shift[b * Ddim + n];
    float4 o;
    o.x = dx * sc + sh; o.y = dy * sc + sh; o.z = dz * sc + sh; o.w = dw * sc + sh;
    reinterpret_cast<float4*>(out + (size_t)row * Ddim)[threadIdx.x] = o;
}

// ---------------- small conditioning GEMM: out[b,n] = act(sum_k A[b,k]*W[k,n] + bias[n]) ----------------
// grid (N/256, B), 256 threads. act: 0 none, 1 relu
__global__ __launch_bounds__(256)
void small_gemm_kernel(const float* __restrict__ A, const float* __restrict__ W,
                       const float* __restrict__ bias, float* __restrict__ out,
                       int K, int N, int act) {
    const int n = blockIdx.x * 256 + threadIdx.x;
    const int b = blockIdx.y;
    const float* a = A + (size_t)b * K;
    float acc = 0.f;
    for (int k = 0; k < K; ++k) acc = fmaf(a[k], W[(size_t)k * N + n], acc);
    acc += bias[n];
    if (act == 1) acc = fmaxf(acc, 0.f);
    out[(size_t)b * N + n] = acc;
}

// ---------------- q -> attention logits: attn[b,h,n] = (q[b,n,:]@qa_w[:,h] + qa_b[h]) * 0.125 ----------------
__global__ __launch_bounds__(256)
void qa_kernel(const float* __restrict__ q, const float* __restrict__ w,
               const float* __restrict__ bias, float* __restrict__ attn) {
    const int warp = threadIdx.x >> 5;
    const int lane = threadIdx.x & 31;
    const int gi = blockIdx.x * 8 + warp;     // 0 .. B*N*H-1
    const int h = gi & 15;
    const int bn = gi >> 4;                   // b*1024+n
    const float* qr = q + (size_t)bn * Ddim;
    float acc = 0.f;
    #pragma unroll 4
    for (int k = lane; k < Ddim; k += 32) acc = fmaf(qr[k], w[k * Hdim + h], acc);
    #pragma unroll
    for (int o = 16; o; o >>= 1) acc += __shfl_xor_sync(0xFFFFFFFFu, acc, o);
    if (lane == 0) {
        const int b = bn >> 10, n = bn & 1023;
        attn[(size_t)b * Hdim * Ndim + h * Ndim + n] = (acc + bias[h]) * INV_SQRT_DEPTH;
    }
}

// ---------------- softmax over N for each (b,h); also writes attn_maps output ----------------
__global__ __launch_bounds__(256)
void softmax_kernel(float* __restrict__ attn, float* __restrict__ out_attn) {
    __shared__ float smem[8];
    const int row = blockIdx.x;  // 0..127
    float4 v = reinterpret_cast<float4*>(attn + (size_t)row * Ndim)[threadIdx.x];
    float m = fmaxf(fmaxf(v.x, v.y), fmaxf(v.z, v.w));
    m = blockReduceMax(m, smem);
    v.x = __expf(v.x - m); v.y = __expf(v.y - m); v.z = __expf(v.z - m); v.w = __expf(v.w - m);
    float s = v.x + v.y + v.z + v.w;
    s = blockReduceSum(s, smem);
    float inv = 1.f / s;
    v.x *= inv; v.y *= inv; v.z *= inv; v.w *= inv;
    reinterpret_cast<float4*>(attn + (size_t)row * Ndim)[threadIdx.x] = v;
    reinterpret_cast<float4*>(out_attn + (size_t)row * Ndim)[threadIdx.x] = v;
}

// ---------------- global_q[b,h,d] = sum_n attn[b,h,n] * q[b,n,h*64+d] ----------------
__global__ __launch_bounds__(256)
void globalq_kernel(const float* __restrict__ attn, const float* __restrict__ q,
                    float* __restrict__ gq) {
    __shared__ float part[256];
    const int bh = blockIdx.x;           // 0..127
    const int b = bh >> 4, h = bh & 15;
    const int g = threadIdx.x >> 6;      // 0..3
    const int d = threadIdx.x & 63;
    const float* ar = attn + (size_t)bh * Ndim;
    float acc = 0.f;
    for (int n = g; n < Ndim; n += 4)
        acc = fmaf(ar[n], q[((size_t)(b * Ndim + n)) * Ddim + h * DEPTH + d], acc);
    part[threadIdx.x] = acc;
    __syncthreads();
    if (g == 0)
        gq[(size_t)bh * DEPTH + d] = part[d] + part[64 + d] + part[128 + d] + part[192 + d];
}

// ---------------- r = broadcast(global_q) * k * v  (gq flat index = b*D + d) ----------------
__global__ __launch_bounds__(256)
void r_kernel(const float* __restrict__ gq, const float* __restrict__ k,
              const float* __restrict__ v, float* __restrict__ r) {
    const size_t idx = (size_t)blockIdx.x * 256 + threadIdx.x;
    const int d = (int)(idx & 1023);
    const int b = (int)(idx >> 20);      // / (N*D)
    r[idx] = gq[b * Ddim + d] * k[idx] * v[idx];
}

// ---------------- host launch ----------------
extern "C" void kernel_launch(void* const* d_in, const int* in_sizes, int n_in,
                              void* d_out, int out_size) {
    const float* inputs = (const float*)d_in[0];
    const float* z      = (const float*)d_in[1];
    const float* n1_hw = (const float*)d_in[2];  const float* n1_hb = (const float*)d_in[3];
    const float* n1_gw = (const float*)d_in[4];  const float* n1_gb = (const float*)d_in[5];
    const float* n1_bw = (const float*)d_in[6];  const float* n1_bb = (const float*)d_in[7];
    const float* wq_w  = (const float*)d_in[8];  const float* wq_b  = (const float*)d_in[9];
    const float* wk_w  = (const float*)d_in[10]; const float* wk_b  = (const float*)d_in[11];
    const float* wv_w  = (const float*)d_in[12]; const float* wv_b  = (const float*)d_in[13];
    const float* qa_w  = (const float*)d_in[14]; const float* qa_b  = (const float*)d_in[15];
    const float* out_w = (const float*)d_in[16]; const float* out_b = (const float*)d_in[17];
    const float* n2_hw = (const float*)d_in[18]; const float* n2_hb = (const float*)d_in[19];
    const float* n2_gw = (const float*)d_in[20]; const float* n2_gb = (const float*)d_in[21];
    const float* n2_bw = (const float*)d_in[22]; const float* n2_bb = (const float*)d_in[23];
    const float* mlp_w1 = (const float*)d_in[24]; const float* mlp_b1 = (const float*)d_in[25];
    const float* mlp_w2 = (const float*)d_in[26]; const float* mlp_b2 = (const float*)d_in[27];

    float* out = (float*)d_out;                          // [B,N,D] flattened
    float* out_attn = out + (size_t)ROWS * Ddim;         // [B,H,N] flattened

    float *xn, *q, *k, *v, *ao, *mlph, *attn, *gq, *hbuf, *sc, *sh;
    cudaGetSymbolAddress((void**)&xn, g_xn);
    cudaGetSymbolAddress((void**)&q, g_q);
    cudaGetSymbolAddress((void**)&k, g_k);
    cudaGetSymbolAddress((void**)&v, g_v);
    cudaGetSymbolAddress((void**)&ao, g_ao);
    cudaGetSymbolAddress((void**)&mlph, g_mlph);
    cudaGetSymbolAddress((void**)&attn, g_attn);
    cudaGetSymbolAddress((void**)&gq, g_gq);
    cudaGetSymbolAddress((void**)&hbuf, g_h);
    cudaGetSymbolAddress((void**)&sc, g_scale);
    cudaGetSymbolAddress((void**)&sh, g_shift);

    const dim3 smallGrid(Ddim / 256, Bdim);

    // norm1 conditioning
    small_gemm_kernel<<<smallGrid, 256>>>(z, n1_hw, n1_hb, hbuf, Ddim, Ddim, 1);
    small_gemm_kernel<<<smallGrid, 256>>>(hbuf, n1_gw, n1_gb, sc, Ddim, Ddim, 0);
    small_gemm_kernel<<<smallGrid, 256>>>(hbuf, n1_bw, n1_bb, sh, Ddim, Ddim, 0);
    // x_norm1
    ln_mod_kernel<<<ROWS, 256>>>(inputs, sc, sh, xn);

    // q, k, v
    dim3 g1(Ddim / BN, ROWS / BM);
    sgemm_kernel<0><<<g1, 256>>>(xn, wq_w, wq_b, nullptr, q, ROWS, Ddim, Ddim);
    sgemm_kernel<0><<<g1, 256>>>(xn, wk_w, wk_b, nullptr, k, ROWS, Ddim, Ddim);
    sgemm_kernel<0><<<g1, 256>>>(xn, wv_w, wv_b, nullptr, v, ROWS, Ddim, Ddim);

    // attention logits + softmax + global q
    qa_kernel<<<(ROWS * Hdim) / 8, 256>>>(q, qa_w, qa_b, attn);
    softmax_kernel<<<Bdim * Hdim, 256>>>(attn, out_attn);
    globalq_kernel<<<Bdim * Hdim, 256>>>(attn, q, gq);

    // r = gq * k * v  (into q buffer)
    r_kernel<<<(ROWS * Ddim) / 256, 256>>>(gq, k, v, q);

    // out proj + residual(inputs) -> attn_out
    sgemm_kernel<1><<<g1, 256>>>(q, out_w, out_b, inputs, ao, ROWS, Ddim, Ddim);

    // norm2 conditioning + x_norm2
    small_gemm_kernel<<<smallGrid, 256>>>(z, n2_hw, n2_hb, hbuf, Ddim, Ddim, 1);
    small_gemm_kernel<<<smallGrid, 256>>>(hbuf, n2_gw, n2_gb, sc, Ddim, Ddim, 0);
    small_gemm_kernel<<<smallGrid, 256>>>(hbuf, n2_bw, n2_bb, sh, Ddim, Ddim, 0);
    ln_mod_kernel<<<ROWS, 256>>>(ao, sc, sh, xn);

    // MLP
    dim3 g2(MLPdim / BN, ROWS / BM);
    sgemm_kernel<2><<<g2, 256>>>(xn, mlp_w1, mlp_b1, nullptr, mlph, ROWS, MLPdim, Ddim);
    dim3 g3(Ddim / BN, ROWS / BM);
    sgemm_kernel<1><<<g3, 256>>>(mlph, mlp_w2, mlp_b2, ao, out, ROWS, Ddim, MLPdim);
}

// round 2
// speedup vs baseline: 2.3132x; 2.3132x over previous
#include <cuda_runtime.h>
#include <math.h>
#include <stdint.h>

// ---------------- constants ----------------
#define Bdim 8
#define Ndim 1024
#define Ddim 1024
#define Hdim 16
#define DEPTH 64
#define MLPdim 4096
#define ROWS (Bdim * Ndim)          // 8192
#define EPSLN 1e-6f
#define INV_SQRT_DEPTH 0.125f

// ---------------- scratch (static device globals; no allocation) ----------------
__device__ float g_xn[ROWS * Ddim];        // x_norm1 / x_norm2
__device__ float g_q[ROWS * Ddim];         // q, later r
__device__ float g_k[ROWS * Ddim];
__device__ float g_v[ROWS * Ddim];
__device__ float g_ao[ROWS * Ddim];        // attn_out
__device__ float g_mlph[ROWS * MLPdim];
__device__ float g_attn[Bdim * Hdim * Ndim];
__device__ float g_gq[Bdim * Hdim * DEPTH];
__device__ float g_h[Bdim * Ddim];
__device__ float g_scale[Bdim * Ddim];
__device__ float g_shift[Bdim * Ddim];

// ---------------- block reduction helpers ----------------
__device__ __forceinline__ float blockReduceSum(float v, float* smem) {
    #pragma unroll
    for (int o = 16; o; o >>= 1) v += __shfl_xor_sync(0xFFFFFFFFu, v, o);
    int wid = threadIdx.x >> 5;
    if ((threadIdx.x & 31) == 0) smem[wid] = v;
    __syncthreads();
    float r = 0.f;
    if (threadIdx.x < 8) r = smem[threadIdx.x];
    if (threadIdx.x < 8) {
        #pragma unroll
        for (int o = 4; o; o >>= 1) r += __shfl_xor_sync(0xFFu, r, o);
        if (threadIdx.x == 0) smem[0] = r;
    }
    __syncthreads();
    r = smem[0];
    __syncthreads();
    return r;
}

__device__ __forceinline__ float blockReduceMax(float v, float* smem) {
    #pragma unroll
    for (int o = 16; o; o >>= 1) v = fmaxf(v, __shfl_xor_sync(0xFFFFFFFFu, v, o));
    int wid = threadIdx.x >> 5;
    if ((threadIdx.x & 31) == 0) smem[wid] = v;
    __syncthreads();
    float r = -1e30f;
    if (threadIdx.x < 8) r = smem[threadIdx.x];
    if (threadIdx.x < 8) {
        #pragma unroll
        for (int o = 4; o; o >>= 1) r = fmaxf(r, __shfl_xor_sync(0xFFu, r, o));
        if (threadIdx.x == 0) smem[0] = r;
    }
    __syncthreads();
    r = smem[0];
    __syncthreads();
    return r;
}

// ---------------- tf32 helpers ----------------
__device__ __forceinline__ uint32_t f2tf(float f) {
    uint32_t u;
    asm("cvt.rna.tf32.f32 %0, %1;" : "=r"(u) : "f"(f));
    return u;
}
__device__ __forceinline__ uint4 cvt4(float4 v) {
    uint4 o;
    o.x = f2tf(v.x); o.y = f2tf(v.y); o.z = f2tf(v.z); o.w = f2tf(v.w);
    return o;
}
__device__ __forceinline__ void mma_tf32(float* d, const uint32_t* a, const uint32_t* b) {
    asm volatile(
        "mma.sync.aligned.m16n8k8.row.col.f32.tf32.tf32.f32 "
        "{%0,%1,%2,%3},{%4,%5,%6,%7},{%8,%9},{%0,%1,%2,%3};"
        : "+f"(d[0]), "+f"(d[1]), "+f"(d[2]), "+f"(d[3])
        : "r"(a[0]), "r"(a[1]), "r"(a[2]), "r"(a[3]), "r"(b[0]), "r"(b[1]));
}

// ---------------- TF32 tensor-core GEMM ----------------
// C[M,N] = epi(A[M,K] @ W[K,N] + bias)
// EPI: 0 = +bias ; 1 = +bias +res ; 2 = gelu(+bias)
// Block tile 128x128, BK=16, 256 threads (8 warps of 64x32 warp tiles).
#define GBK 16
#define AS_STRIDE 20     // 16 + 4 pad (floats) -> conflict-free frag reads
#define BS_STRIDE 136    // 128 + 8 pad (floats) -> conflict-free frag reads

template <int EPI>
__global__ __launch_bounds__(256, 2)
void mma_gemm(const float* __restrict__ A, const float* __restrict__ W,
              const float* __restrict__ bias, const float* __restrict__ res,
              float* __restrict__ C, int M, int N, int K) {
    __shared__ uint32_t As[2][128 * AS_STRIDE];
    __shared__ uint32_t Bs[2][GBK * BS_STRIDE];

    const int tid = threadIdx.x;
    const int lane = tid & 31;
    const int warp = tid >> 5;
    const int wm = warp >> 2;        // 0..1
    const int wn = warp & 3;         // 0..3
    const int g = lane >> 2;         // 0..7
    const int c = lane & 3;          // 0..3

    // loader indices
    const int aRow = tid >> 2;               // 0..63 (two passes of 64 rows)
    const int aCol = (tid & 3) << 2;         // 0,4,8,12
    const int bK = tid >> 5;                 // 0..7 (two passes of 8 k-rows)
    const int bCol = (tid & 31) << 2;        // 0..124

    const float* Aptr = A + (size_t)(blockIdx.y * 128 + aRow) * K + aCol;
    const float* Bptr = W + (size_t)bK * N + blockIdx.x * 128 + bCol;

    float acc[4][4][4];
    #pragma unroll
    for (int i = 0; i < 4; ++i)
        #pragma unroll
        for (int j = 0; j < 4; ++j)
            #pragma unroll
            for (int q = 0; q < 4; ++q) acc[i][j][q] = 0.f;

    float4 aLd[2], bLd[2];

    // prologue: load tile 0
    aLd[0] = *reinterpret_cast<const float4*>(Aptr);
    aLd[1] = *reinterpret_cast<const float4*>(Aptr + (size_t)64 * K);
    bLd[0] = *reinterpret_cast<const float4*>(Bptr);
    bLd[1] = *reinterpret_cast<const float4*>(Bptr + (size_t)8 * N);
    *reinterpret_cast<uint4*>(&As[0][aRow * AS_STRIDE + aCol]) = cvt4(aLd[0]);
    *reinterpret_cast<uint4*>(&As[0][(aRow + 64) * AS_STRIDE + aCol]) = cvt4(aLd[1]);
    *reinterpret_cast<uint4*>(&Bs[0][bK * BS_STRIDE + bCol]) = cvt4(bLd[0]);
    *reinterpret_cast<uint4*>(&Bs[0][(bK + 8) * BS_STRIDE + bCol]) = cvt4(bLd[1]);
    __syncthreads();

    int cur = 0;
    for (int kt = GBK; kt <= K; kt += GBK) {
        const bool hasNext = (kt < K);
        if (hasNext) {
            aLd[0] = *reinterpret_cast<const float4*>(Aptr + kt);
            aLd[1] = *reinterpret_cast<const float4*>(Aptr + kt + (size_t)64 * K);
            bLd[0] = *reinterpret_cast<const float4*>(Bptr + (size_t)kt * N);
            bLd[1] = *reinterpret_cast<const float4*>(Bptr + (size_t)(kt + 8) * N);
        }

        // compute on buffer `cur`
        const uint32_t* as = As[cur];
        const uint32_t* bs = Bs[cur];
        #pragma unroll
        for (int ks = 0; ks < 2; ++ks) {
            const int k8 = ks * 8;
            uint32_t af[4][4], bf[4][2];
            #pragma unroll
            for (int i = 0; i < 4; ++i) {
                const int m = wm * 64 + i * 16 + g;
                af[i][0] = as[m * AS_STRIDE + k8 + c];
                af[i][1] = as[(m + 8) * AS_STRIDE + k8 + c];
                af[i][2] = as[m * AS_STRIDE + k8 + c + 4];
                af[i][3] = as[(m + 8) * AS_STRIDE + k8 + c + 4];
            }
            #pragma unroll
            for (int j = 0; j < 4; ++j) {
                const int n = wn * 32 + j * 8 + g;
                bf[j][0] = bs[(k8 + c) * BS_STRIDE + n];
                bf[j][1] = bs[(k8 + c + 4) * BS_STRIDE + n];
            }
            #pragma unroll
            for (int i = 0; i < 4; ++i)
                #pragma unroll
                for (int j = 0; j < 4; ++j)
                    mma_tf32(acc[i][j], af[i], bf[j]);
        }

        if (hasNext) {
            const int nxt = cur ^ 1;
            *reinterpret_cast<uint4*>(&As[nxt][aRow * AS_STRIDE + aCol]) = cvt4(aLd[0]);
            *reinterpret_cast<uint4*>(&As[nxt][(aRow + 64) * AS_STRIDE + aCol]) = cvt4(aLd[1]);
            *reinterpret_cast<uint4*>(&Bs[nxt][bK * BS_STRIDE + bCol]) = cvt4(bLd[0]);
            *reinterpret_cast<uint4*>(&Bs[nxt][(bK + 8) * BS_STRIDE + bCol]) = cvt4(bLd[1]);
            __syncthreads();
            cur = nxt;
        }
    }

    // epilogue
    #pragma unroll
    for (int i = 0; i < 4; ++i) {
        const int row0 = blockIdx.y * 128 + wm * 64 + i * 16 + g;
        #pragma unroll
        for (int j = 0; j < 4; ++j) {
            const int col = blockIdx.x * 128 + wn * 32 + j * 8 + 2 * c;
            const float b0 = bias[col], b1 = bias[col + 1];
            #pragma unroll
            for (int half = 0; half < 2; ++half) {
                const int row = row0 + half * 8;
                float v0 = acc[i][j][half * 2 + 0] + b0;
                float v1 = acc[i][j][half * 2 + 1] + b1;
                if (EPI == 1) {
                    const float2 rr = *reinterpret_cast<const float2*>(res + (size_t)row * N + col);
                    v0 += rr.x; v1 += rr.y;
                }
                if (EPI == 2) {
                    v0 = 0.5f * v0 * (1.f + erff(v0 * 0.7071067811865475f));
                    v1 = 0.5f * v1 * (1.f + erff(v1 * 0.7071067811865475f));
                }
                float2 o; o.x = v0; o.y = v1;
                *reinterpret_cast<float2*>(C + (size_t)row * N + col) = o;
            }
        }
    }
}

// ---------------- layernorm (no affine) + per-row scale/shift modulation ----------------
__global__ __launch_bounds__(256)
void ln_mod_kernel(const float* __restrict__ x, const float* __restrict__ scale,
                   const float* __restrict__ shift, float* __restrict__ out) {
    __shared__ float smem[8];
    const int row = blockIdx.x;          // 0..8191
    const int b = row >> 10;
    const int n = row & 1023;
    float4 v = reinterpret_cast<const float4*>(x + (size_t)row * Ddim)[threadIdx.x];
    float s = v.x + v.y + v.z + v.w;
    float mean = blockReduceSum(s, smem) * (1.f / Ddim);
    float dx = v.x - mean, dy = v.y - mean, dz = v.z - mean, dw = v.w - mean;
    float sq = dx * dx + dy * dy + dz * dz + dw * dw;
    float var = blockReduceSum(sq, smem) * (1.f / Ddim);
    float rstd = rsqrtf(var + EPSLN);
    float sc = scale[b * Ddim + n] * rstd;
    float sh = shift[b * Ddim + n];
    float4 o;
    o.x = dx * sc + sh; o.y = dy * sc + sh; o.z = dz * sc + sh; o.w = dw * sc + sh;
    reinterpret_cast<float4*>(out + (size_t)row * Ddim)[threadIdx.x] = o;
}

// ---------------- small conditioning GEMM ----------------
__global__ __launch_bounds__(256)
void small_gemm_kernel(const float* __restrict__ A, const float* __restrict__ W,
                       const float* __restrict__ bias, float* __restrict__ out,
                       int K, int N, int act) {
    const int n = blockIdx.x * 256 + threadIdx.x;
    const int b = blockIdx.y;
    const float* a = A + (size_t)b * K;
    float acc = 0.f;
    for (int k = 0; k < K; ++k) acc = fmaf(a[k], W[(size_t)k * N + n], acc);
    acc += bias[n];
    if (act == 1) acc = fmaxf(acc, 0.f);
    out[(size_t)b * N + n] = acc;
}

// ---------------- q -> attention logits ----------------
__global__ __launch_bounds__(256)
void qa_kernel(const float* __restrict__ q, const float* __restrict__ w,
               const float* __restrict__ bias, float* __restrict__ attn) {
    const int warp = threadIdx.x >> 5;
    const int lane = threadIdx.x & 31;
    const int gi = blockIdx.x * 8 + warp;     // 0 .. B*N*H-1
    const int h = gi & 15;
    const int bn = gi >> 4;                   // b*1024+n
    const float* qr = q + (size_t)bn * Ddim;
    float acc = 0.f;
    #pragma unroll 4
    for (int k = lane; k < Ddim; k += 32) acc = fmaf(qr[k], w[k * Hdim + h], acc);
    #pragma unroll
    for (int o = 16; o; o >>= 1) acc += __shfl_xor_sync(0xFFFFFFFFu, acc, o);
    if (lane == 0) {
        const int b = bn >> 10, n = bn & 1023;
        attn[(size_t)b * Hdim * Ndim + h * Ndim + n] = (acc + bias[h]) * INV_SQRT_DEPTH;
    }
}

// ---------------- softmax over N for each (b,h); also writes attn_maps output ----------------
__global__ __launch_bounds__(256)
void softmax_kernel(float* __restrict__ attn, float* __restrict__ out_attn) {
    __shared__ float smem[8];
    const int row = blockIdx.x;  // 0..127
    float4 v = reinterpret_cast<float4*>(attn + (size_t)row * Ndim)[threadIdx.x];
    float m = fmaxf(fmaxf(v.x, v.y), fmaxf(v.z, v.w));
    m = blockReduceMax(m, smem);
    v.x = __expf(v.x - m); v.y = __expf(v.y - m); v.z = __expf(v.z - m); v.w = __expf(v.w - m);
    float s = v.x + v.y + v.z + v.w;
    s = blockReduceSum(s, smem);
    float inv = 1.f / s;
    v.x *= inv; v.y *= inv; v.z *= inv; v.w *= inv;
    reinterpret_cast<float4*>(attn + (size_t)row * Ndim)[threadIdx.x] = v;
    reinterpret_cast<float4*>(out_attn + (size_t)row * Ndim)[threadIdx.x] = v;
}

// ---------------- global_q[b,h,d] = sum_n attn[b,h,n] * q[b,n,h*64+d] ----------------
__global__ __launch_bounds__(256)
void globalq_kernel(const float* __restrict__ attn, const float* __restrict__ q,
                    float* __restrict__ gq) {
    __shared__ float part[256];
    const int bh = blockIdx.x;           // 0..127
    const int b = bh >> 4, h = bh & 15;
    const int g = threadIdx.x >> 6;      // 0..3
    const int d = threadIdx.x & 63;
    const float* ar = attn + (size_t)bh * Ndim;
    float acc = 0.f;
    for (int n = g; n < Ndim; n += 4)
        acc = fmaf(ar[n], q[((size_t)(b * Ndim + n)) * Ddim + h * DEPTH + d], acc);
    part[threadIdx.x] = acc;
    __syncthreads();
    if (g == 0)
        gq[(size_t)bh * DEPTH + d] = part[d] + part[64 + d] + part[128 + d] + part[192 + d];
}

// ---------------- r = broadcast(global_q) * k * v ----------------
__global__ __launch_bounds__(256)
void r_kernel(const float* __restrict__ gq, const float* __restrict__ k,
              const float* __restrict__ v, float* __restrict__ r) {
    const size_t idx = (size_t)blockIdx.x * 256 + threadIdx.x;
    const int d = (int)(idx & 1023);
    const int b = (int)(idx >> 20);      // / (N*D)
    r[idx] = gq[b * Ddim + d] * k[idx] * v[idx];
}

// ---------------- host launch ----------------
extern "C" void kernel_launch(void* const* d_in, const int* in_sizes, int n_in,
                              void* d_out, int out_size) {
    const float* inputs = (const float*)d_in[0];
    const float* z      = (const float*)d_in[1];
    const float* n1_hw = (const float*)d_in[2];  const float* n1_hb = (const float*)d_in[3];
    const float* n1_gw = (const float*)d_in[4];  const float* n1_gb = (const float*)d_in[5];
    const float* n1_bw = (const float*)d_in[6];  const float* n1_bb = (const float*)d_in[7];
    const float* wq_w  = (const float*)d_in[8];  const float* wq_b  = (const float*)d_in[9];
    const float* wk_w  = (const float*)d_in[10]; const float* wk_b  = (const float*)d_in[11];
    const float* wv_w  = (const float*)d_in[12]; const float* wv_b  = (const float*)d_in[13];
    const float* qa_w  = (const float*)d_in[14]; const float* qa_b  = (const float*)d_in[15];
    const float* out_w = (const float*)d_in[16]; const float* out_b = (const float*)d_in[17];
    const float* n2_hw = (const float*)d_in[18]; const float* n2_hb = (const float*)d_in[19];
    const float* n2_gw = (const float*)d_in[20]; const float* n2_gb = (const float*)d_in[21];
    const float* n2_bw = (const float*)d_in[22]; const float* n2_bb = (const float*)d_in[23];
    const float* mlp_w1 = (const float*)d_in[24]; const float* mlp_b1 = (const float*)d_in[25];
    const float* mlp_w2 = (const float*)d_in[26]; const float* mlp_b2 = (const float*)d_in[27];

    float* out = (float*)d_out;                          // [B,N,D] flattened
    float* out_attn = out + (size_t)ROWS * Ddim;         // [B,H,N] flattened

    float *xn, *q, *k, *v, *ao, *mlph, *attn, *gq, *hbuf, *sc, *sh;
    cudaGetSymbolAddress((void**)&xn, g_xn);
    cudaGetSymbolAddress((void**)&q, g_q);
    cudaGetSymbolAddress((void**)&k, g_k);
    cudaGetSymbolAddress((void**)&v, g_v);
    cudaGetSymbolAddress((void**)&ao, g_ao);
    cudaGetSymbolAddress((void**)&mlph, g_mlph);
    cudaGetSymbolAddress((void**)&attn, g_attn);
    cudaGetSymbolAddress((void**)&gq, g_gq);
    cudaGetSymbolAddress((void**)&hbuf, g_h);
    cudaGetSymbolAddress((void**)&sc, g_scale);
    cudaGetSymbolAddress((void**)&sh, g_shift);

    const dim3 smallGrid(Ddim / 256, Bdim);

    // norm1 conditioning
    small_gemm_kernel<<<smallGrid, 256>>>(z, n1_hw, n1_hb, hbuf, Ddim, Ddim, 1);
    small_gemm_kernel<<<smallGrid, 256>>>(hbuf, n1_gw, n1_gb, sc, Ddim, Ddim, 0);
    small_gemm_kernel<<<smallGrid, 256>>>(hbuf, n1_bw, n1_bb, sh, Ddim, Ddim, 0);
    // x_norm1
    ln_mod_kernel<<<ROWS, 256>>>(inputs, sc, sh, xn);

    // q, k, v (TF32 tensor cores)
    dim3 g1(Ddim / 128, ROWS / 128);
    mma_gemm<0><<<g1, 256>>>(xn, wq_w, wq_b, nullptr, q, ROWS, Ddim, Ddim);
    mma_gemm<0><<<g1, 256>>>(xn, wk_w, wk_b, nullptr, k, ROWS, Ddim, Ddim);
    mma_gemm<0><<<g1, 256>>>(xn, wv_w, wv_b, nullptr, v, ROWS, Ddim, Ddim);

    // attention logits + softmax + global q
    qa_kernel<<<(ROWS * Hdim) / 8, 256>>>(q, qa_w, qa_b, attn);
    softmax_kernel<<<Bdim * Hdim, 256>>>(attn, out_attn);
    globalq_kernel<<<Bdim * Hdim, 256>>>(attn, q, gq);

    // r = gq * k * v  (into q buffer)
    r_kernel<<<(ROWS * Ddim) / 256, 256>>>(gq, k, v, q);

    // out proj + residual(inputs) -> attn_out
    mma_gemm<1><<<g1, 256>>>(q, out_w, out_b, inputs, ao, ROWS, Ddim, Ddim);

    // norm2 conditioning + x_norm2
    small_gemm_kernel<<<smallGrid, 256>>>(z, n2_hw, n2_hb, hbuf, Ddim, Ddim, 1);
    small_gemm_kernel<<<smallGrid, 256>>>(hbuf, n2_gw, n2_gb, sc, Ddim, Ddim, 0);
    small_gemm_kernel<<<smallGrid, 256>>>(hbuf, n2_bw, n2_bb, sh, Ddim, Ddim, 0);
    ln_mod_kernel<<<ROWS, 256>>>(ao, sc, sh, xn);

    // MLP (TF32 tensor cores)
    dim3 g2(MLPdim / 128, ROWS / 128);
    mma_gemm<2><<<g2, 256>>>(xn, mlp_w1, mlp_b1, nullptr, mlph, ROWS, MLPdim, Ddim);
    dim3 g3(Ddim / 128, ROWS / 128);
    mma_gemm<1><<<g3, 256>>>(mlph, mlp_w2, mlp_b2, ao, out, ROWS, Ddim, MLPdim);
}